// round 8
// baseline (speedup 1.0000x reference)
#include <cuda_runtime.h>
#include <math.h>

#define LLEN 8192
#define BATCH 256
#define TL 1024
#define EPSB 1e-5f
#define XROW 1140
#define FROW 1088
#define NCHUNK 8

// ---------------- device scratch ----------------
__device__ float g_gpart[NCHUNK * BATCH * 256];
__device__ float g_Weff[BATCH * 256];

// ---------------------------------------------------------------------------
// Kernel 1: partial gram of c0, 4x4 register tiling.
// Grid (NCHUNK, BATCH), 256 threads.
// t -> rp=t>>6 (4 row-groups), cg=(t>>4)&3 (4 col-groups), p=t&15 (pos slice).
// Butterfly-reduce over p (lane bits 0-3), lanes p==0 write 16 values.
// ---------------------------------------------------------------------------
__global__ __launch_bounds__(256) void gram_kernel(
    const float* __restrict__ x,
    const float* __restrict__ wc1, const float* __restrict__ g1,
    const float* __restrict__ bt1, const float* __restrict__ m1,
    const float* __restrict__ v1)
{
    __shared__ float c0s[16 * 260];
    __shared__ float u1s[64];
    __shared__ float sh1s[16];

    const int b = blockIdx.y;
    const int chunk = blockIdx.x;
    const int t = threadIdx.x;
    const int rp = t >> 6;
    const int cg = (t >> 4) & 3;
    const int p  = t & 15;

    if (t < 16) {
        float inv1 = g1[t] * rsqrtf(v1[t] + EPSB);
        sh1s[t] = bt1[t] - m1[t] * inv1;
        #pragma unroll
        for (int i = 0; i < 4; i++) u1s[t * 4 + i] = inv1 * wc1[t * 4 + i];
    }
    __syncthreads();

    // volatile: keep weights in SMEM (regs stay ~32-64, occupancy high)
    const volatile float* uv = u1s;
    const volatile float* sv = sh1s;

    float acc[4][4];
    #pragma unroll
    for (int i = 0; i < 4; i++)
        #pragma unroll
        for (int j = 0; j < 4; j++) acc[i][j] = 0.f;

    for (int ch = 0; ch < 4; ch++) {
        int pos = (chunk * 4 + ch) * 256 + t;
        float xv0 = x[(b * 4 + 0) * LLEN + pos];
        float xv1 = x[(b * 4 + 1) * LLEN + pos];
        float xv2 = x[(b * 4 + 2) * LLEN + pos];
        float xv3 = x[(b * 4 + 3) * LLEN + pos];
        __syncthreads();
        #pragma unroll
        for (int c = 0; c < 16; c++) {
            float v = sv[c] + uv[c * 4 + 0] * xv0 + uv[c * 4 + 1] * xv1
                            + uv[c * 4 + 2] * xv2 + uv[c * 4 + 3] * xv3;
            c0s[c * 260 + t] = fmaxf(v, 0.f);
        }
        __syncthreads();
        #pragma unroll
        for (int m = 0; m < 4; m++) {
            int j4 = p + 16 * m;
            float4 ra[4], rb[4];
            #pragma unroll
            for (int i = 0; i < 4; i++)
                ra[i] = ((const float4*)(c0s + (4 * rp + i) * 260))[j4];
            #pragma unroll
            for (int j = 0; j < 4; j++)
                rb[j] = ((const float4*)(c0s + (4 * cg + j) * 260))[j4];
            #pragma unroll
            for (int i = 0; i < 4; i++)
                #pragma unroll
                for (int j = 0; j < 4; j++)
                    acc[i][j] += ra[i].x * rb[j].x + ra[i].y * rb[j].y
                               + ra[i].z * rb[j].z + ra[i].w * rb[j].w;
        }
    }

    // reduce over the 16 position slices (lane bits 0..3)
    #pragma unroll
    for (int i = 0; i < 4; i++)
        #pragma unroll
        for (int j = 0; j < 4; j++) {
            float v = acc[i][j];
            v += __shfl_xor_sync(0xffffffffu, v, 1);
            v += __shfl_xor_sync(0xffffffffu, v, 2);
            v += __shfl_xor_sync(0xffffffffu, v, 4);
            v += __shfl_xor_sync(0xffffffffu, v, 8);
            acc[i][j] = v;
        }
    if (p == 0) {
        float* dst = g_gpart + (chunk * BATCH + b) * 256;
        #pragma unroll
        for (int i = 0; i < 4; i++)
            #pragma unroll
            for (int j = 0; j < 4; j++)
                dst[(4 * rp + i) * 16 + 4 * cg + j] = acc[i][j];
    }
}

// ---------------------------------------------------------------------------
// Kernel 2: sum partials, softmax + fold into W_eff
// ---------------------------------------------------------------------------
__global__ __launch_bounds__(256) void fold_kernel(
    const float* __restrict__ beta_cam,
    const float* __restrict__ wc2, const float* __restrict__ g2,
    const float* __restrict__ v2)
{
    __shared__ float gsm[256];
    __shared__ float asmem[256];
    const int b = blockIdx.x;
    const int t = threadIdx.x;

    float s = 0.f;
    #pragma unroll
    for (int ch = 0; ch < NCHUNK; ch++)
        s += g_gpart[(ch * BATCH + b) * 256 + t];
    gsm[t] = s;
    __syncthreads();

    if (t < 16) {
        float rmin = 1e30f;
        #pragma unroll
        for (int d = 0; d < 16; d++) rmin = fminf(rmin, gsm[t * 16 + d]);
        float e[16];
        float ssum = 0.f;
        #pragma unroll
        for (int d = 0; d < 16; d++) { e[d] = expf(rmin - gsm[t * 16 + d]); ssum += e[d]; }
        float invs = 1.f / ssum;
        #pragma unroll
        for (int d = 0; d < 16; d++) asmem[t * 16 + d] = e[d] * invs;
    }
    __syncthreads();

    const int cg = t >> 4;
    const int dg = t & 15;
    float inv2c = g2[cg] * rsqrtf(v2[cg] + EPSB);
    float beta = beta_cam[0];
    float acc = 0.f;
    #pragma unroll
    for (int e = 0; e < 16; e++) acc += wc2[cg * 16 + e] * asmem[e * 16 + dg];
    g_Weff[b * 256 + t] = inv2c * (beta * acc + wc2[cg * 16 + dg]);
}

// ---------------------------------------------------------------------------
// Kernel 3: fused ConvFusion + attention epilogue.
// TL=1024, 256 threads, 4 pos/thread, COMBINED fea1/fea2 d-loop sharing one
// win[36]; weights loaded one float4 at a time from original [c][d][k] layout.
// No swizzle (consecutive float4 reads / stride-17 scalar writes are
// conflict-free as-is).
// SMEM (floats):
//   xs [0,4560) | f0s [4560,13264) | w00s [13264,14288) | w01s [14288,15312)
//   w02s [15312,16336) | weffs [16336,16592) | u1s [16592,16656)
//   sh1s [16656,16672) | sh2s [16672,16688) | b00s/b01s/b02s [16688,16712)
// total 16712 floats = 66848 B (2 CTA/SM)
// ---------------------------------------------------------------------------
#define SMEM_FLOATS 16712

__global__ __launch_bounds__(256, 2) void main_kernel(
    const float* __restrict__ x,
    const float* __restrict__ w00, const float* __restrict__ b00,
    const float* __restrict__ w01, const float* __restrict__ b01,
    const float* __restrict__ w02, const float* __restrict__ b02,
    const float* __restrict__ wc1, const float* __restrict__ g1,
    const float* __restrict__ bt1, const float* __restrict__ m1,
    const float* __restrict__ v1,
    const float* __restrict__ g2, const float* __restrict__ bt2,
    const float* __restrict__ m2, const float* __restrict__ v2,
    float* __restrict__ out)
{
    extern __shared__ float sm[];
    float* xs    = sm;
    float* f0s   = sm + 4560;
    float* w00s  = sm + 13264;
    float* w01s  = sm + 14288;
    float* w02s  = sm + 15312;
    float* weffs = sm + 16336;
    float* u1s   = sm + 16592;
    float* sh1s  = sm + 16656;
    float* sh2s  = sm + 16672;
    float* b00s  = sm + 16688;
    float* b01s  = sm + 16696;
    float* b02s  = sm + 16704;

    const int t = threadIdx.x;
    const int l0 = blockIdx.x * TL;
    const int b = blockIdx.y;

    // ---- phase A: weights (raw layouts) ----
    for (int i = t; i < 1024; i += 256) {
        w00s[i] = w00[i];
        w01s[i] = w01[i];
        w02s[i] = w02[i];
    }
    if (t < 64) {
        int c = t >> 2;
        float inv1 = g1[c] * rsqrtf(v1[c] + EPSB);
        u1s[t] = inv1 * wc1[t];
    }
    if (t < 16) {
        float inv1 = g1[t] * rsqrtf(v1[t] + EPSB);
        sh1s[t] = bt1[t] - m1[t] * inv1;
        float inv2 = g2[t] * rsqrtf(v2[t] + EPSB);
        sh2s[t] = bt2[t] - m2[t] * inv2;
    }
    weffs[t] = g_Weff[b * 256 + t];
    if (t < 8) { b00s[t] = b00[t]; b01s[t] = b01[t]; b02s[t] = b02[t]; }

    // ---- phase B: x tile with halo ----
    for (int idx = t; idx < 4 * XROW; idx += 256) {
        int i = idx / XROW, o = idx - i * XROW;
        int g = l0 - 32 + o;
        xs[idx] = (g >= 0 && g < LLEN) ? x[(b * 4 + i) * LLEN + g] : 0.f;
    }
    __syncthreads();

    // ---- phase C: fea0. warp = channel d, 2 passes x 17 positions/lane ----
    {
        const int d = t >> 5;
        const int lane = t & 31;
        const float bv = b00s[d];
        #pragma unroll
        for (int pass = 0; pass < 2; pass++) {
            const int jj0 = pass * 544 + lane * 17;
            float acc[17];
            #pragma unroll
            for (int p = 0; p < 17; p++) acc[p] = bv;
            #pragma unroll
            for (int i = 0; i < 4; i++) {
                float xw[48];
                const float* xrow = xs + i * XROW + jj0 + 2;
                #pragma unroll
                for (int m = 0; m < 48; m++) xw[m] = xrow[m];
                float wreg[32];
                const float4* wr4 = (const float4*)(w00s + (d * 4 + i) * 32);
                #pragma unroll
                for (int q = 0; q < 8; q++) {
                    float4 wv = wr4[q];
                    wreg[4 * q] = wv.x; wreg[4 * q + 1] = wv.y;
                    wreg[4 * q + 2] = wv.z; wreg[4 * q + 3] = wv.w;
                }
                #pragma unroll
                for (int k = 0; k < 32; k++) {
                    float wv = wreg[k];
                    #pragma unroll
                    for (int p = 0; p < 17; p++) acc[p] += wv * xw[p + k];
                }
            }
            #pragma unroll
            for (int p = 0; p < 17; p++) {
                int jj = jj0 + p;
                int j = l0 - 14 + jj;
                f0s[d * FROW + jj] = (j >= 0 && j <= LLEN) ? acc[p] : 0.f;
            }
        }
    }
    __syncthreads();

    // ---- phase D: combined fea1 + fea2, 4 positions/thread ----
    float acc1[4][8], acc2[4][8];
    #pragma unroll
    for (int c = 0; c < 8; c++) {
        float bA = b01s[c], bB = b02s[c];
        #pragma unroll
        for (int p = 0; p < 4; p++) { acc1[p][c] = bA; acc2[p][c] = bB; }
    }

    #pragma unroll 1
    for (int d = 0; d < 8; d++) {
        float win[36];   // f0[d][4t .. 4t+35]
        const float4* fr = (const float4*)(f0s + d * FROW) + t;
        #pragma unroll
        for (int q = 0; q < 9; q++) {
            float4 v = fr[q];
            win[4 * q] = v.x; win[4 * q + 1] = v.y;
            win[4 * q + 2] = v.z; win[4 * q + 3] = v.w;
        }
        #pragma unroll
        for (int c = 0; c < 8; c++) {
            const float4* wa = (const float4*)(w01s + (c * 8 + d) * 16);
            #pragma unroll
            for (int kq = 0; kq < 4; kq++) {
                float4 w = wa[kq];
                #pragma unroll
                for (int p = 0; p < 4; p++) {
                    float s = acc1[p][c];
                    s += w.x * win[7 + 4 * kq + p];
                    s += w.y * win[8 + 4 * kq + p];
                    s += w.z * win[9 + 4 * kq + p];
                    s += w.w * win[10 + 4 * kq + p];
                    acc1[p][c] = s;
                }
            }
            const float4* wb = (const float4*)(w02s + (c * 8 + d) * 16);
            #pragma unroll
            for (int kq = 0; kq < 4; kq++) {
                float4 w = wb[kq];
                #pragma unroll
                for (int p = 0; p < 4; p++) {
                    float s = acc2[p][c];
                    s += w.x * win[8 * kq + p];
                    s += w.y * win[8 * kq + 2 + p];
                    s += w.z * win[8 * kq + 4 + p];
                    s += w.w * win[8 * kq + 6 + p];
                    acc2[p][c] = s;
                }
            }
        }
    }

    // ---- epilogue: c0 via LDG (per position-pair), weff, store ----
    const int lbase = l0 + 4 * t;
    #pragma unroll
    for (int pp = 0; pp < 2; pp++) {
        float xv[4][2];
        #pragma unroll
        for (int i = 0; i < 4; i++) {
            float2 v = *(const float2*)(x + (b * 4 + i) * LLEN + lbase + 2 * pp);
            xv[i][0] = v.x; xv[i][1] = v.y;
        }
        float c0v[2][16];
        #pragma unroll
        for (int p2 = 0; p2 < 2; p2++) {
            float x0 = xv[0][p2], x1 = xv[1][p2], x2 = xv[2][p2], x3 = xv[3][p2];
            #pragma unroll
            for (int c = 0; c < 16; c++) {
                float4 u = *(const float4*)(u1s + c * 4);
                float v = sh1s[c] + u.x * x0 + u.y * x1 + u.z * x2 + u.w * x3;
                c0v[p2][c] = fmaxf(v, 0.f);
            }
        }
        const int l = lbase + 2 * pp;
        #pragma unroll
        for (int c = 0; c < 16; c++) {
            float s0 = sh2s[c], s1 = sh2s[c];
            #pragma unroll
            for (int dq = 0; dq < 16; dq += 4) {
                float4 wv = *(const float4*)(weffs + c * 16 + dq);
                s0 += wv.x * c0v[0][dq] + wv.y * c0v[0][dq + 1]
                    + wv.z * c0v[0][dq + 2] + wv.w * c0v[0][dq + 3];
                s1 += wv.x * c0v[1][dq] + wv.y * c0v[1][dq + 1]
                    + wv.z * c0v[1][dq + 2] + wv.w * c0v[1][dq + 3];
            }
            float f0v, f1v;
            if (c < 8) {
                f0v = acc1[2 * pp][c];
                f1v = acc1[2 * pp + 1][c];
            } else {
                f0v = acc2[2 * pp][c - 8];
                f1v = acc2[2 * pp + 1][c - 8];
                if (l == 0 || l >= LLEN - 2) f0v = 0.f;
                if (l + 1 >= LLEN - 2) f1v = 0.f;
            }
            *(float2*)(out + (b * 16 + c) * LLEN + l) =
                make_float2(f0v + fmaxf(s0, 0.f), f1v + fmaxf(s1, 0.f));
        }
    }
}

// ---------------------------------------------------------------------------
extern "C" void kernel_launch(void* const* d_in, const int* in_sizes, int n_in,
                              void* d_out, int out_size)
{
    const float* x        = (const float*)d_in[0];
    const float* w00      = (const float*)d_in[1];
    const float* b00      = (const float*)d_in[2];
    const float* w01      = (const float*)d_in[3];
    const float* b01      = (const float*)d_in[4];
    const float* w02      = (const float*)d_in[5];
    const float* b02      = (const float*)d_in[6];
    const float* wc1      = (const float*)d_in[7];
    const float* g1       = (const float*)d_in[8];
    const float* bt1      = (const float*)d_in[9];
    const float* m1       = (const float*)d_in[10];
    const float* v1       = (const float*)d_in[11];
    const float* beta_cam = (const float*)d_in[12];
    const float* wc2      = (const float*)d_in[13];
    const float* g2       = (const float*)d_in[14];
    const float* bt2      = (const float*)d_in[15];
    const float* m2       = (const float*)d_in[16];
    const float* v2       = (const float*)d_in[17];
    float* out = (float*)d_out;

    cudaFuncSetAttribute(main_kernel,
                         cudaFuncAttributeMaxDynamicSharedMemorySize,
                         SMEM_FLOATS * 4);

    dim3 ggrid(NCHUNK, BATCH);
    gram_kernel<<<ggrid, 256>>>(x, wc1, g1, bt1, m1, v1);
    fold_kernel<<<BATCH, 256>>>(beta_cam, wc2, g2, v2);
    dim3 grid(LLEN / TL, BATCH);
    main_kernel<<<grid, 256, SMEM_FLOATS * 4>>>(
        x, w00, b00, w01, b01, w02, b02,
        wc1, g1, bt1, m1, v1, g2, bt2, m2, v2, out);
}

// round 9
// speedup vs baseline: 2.1705x; 2.1705x over previous
#include <cuda_runtime.h>
#include <math.h>

#define LLEN 8192
#define BATCH 256
#define TL 512
#define EPSB 1e-5f
#define NCHUNK 8

// ---------------- device scratch ----------------
__device__ float g_gpart[NCHUNK * BATCH * 256];
__device__ float g_Weff[BATCH * 256];

// ---------------------------------------------------------------------------
// Kernel 1: partial gram of c0, 4x4 register tiling. (R8, measured 69us)
// Grid (NCHUNK, BATCH), 256 threads.
// ---------------------------------------------------------------------------
__global__ __launch_bounds__(256) void gram_kernel(
    const float* __restrict__ x,
    const float* __restrict__ wc1, const float* __restrict__ g1,
    const float* __restrict__ bt1, const float* __restrict__ m1,
    const float* __restrict__ v1)
{
    __shared__ float c0s[16 * 260];
    __shared__ float u1s[64];
    __shared__ float sh1s[16];

    const int b = blockIdx.y;
    const int chunk = blockIdx.x;
    const int t = threadIdx.x;
    const int rp = t >> 6;
    const int cg = (t >> 4) & 3;
    const int p  = t & 15;

    if (t < 16) {
        float inv1 = g1[t] * rsqrtf(v1[t] + EPSB);
        sh1s[t] = bt1[t] - m1[t] * inv1;
        #pragma unroll
        for (int i = 0; i < 4; i++) u1s[t * 4 + i] = inv1 * wc1[t * 4 + i];
    }
    __syncthreads();

    const volatile float* uv = u1s;
    const volatile float* sv = sh1s;

    float acc[4][4];
    #pragma unroll
    for (int i = 0; i < 4; i++)
        #pragma unroll
        for (int j = 0; j < 4; j++) acc[i][j] = 0.f;

    for (int ch = 0; ch < 4; ch++) {
        int pos = (chunk * 4 + ch) * 256 + t;
        float xv0 = x[(b * 4 + 0) * LLEN + pos];
        float xv1 = x[(b * 4 + 1) * LLEN + pos];
        float xv2 = x[(b * 4 + 2) * LLEN + pos];
        float xv3 = x[(b * 4 + 3) * LLEN + pos];
        __syncthreads();
        #pragma unroll
        for (int c = 0; c < 16; c++) {
            float v = sv[c] + uv[c * 4 + 0] * xv0 + uv[c * 4 + 1] * xv1
                            + uv[c * 4 + 2] * xv2 + uv[c * 4 + 3] * xv3;
            c0s[c * 260 + t] = fmaxf(v, 0.f);
        }
        __syncthreads();
        #pragma unroll
        for (int m = 0; m < 4; m++) {
            int j4 = p + 16 * m;
            float4 ra[4], rb[4];
            #pragma unroll
            for (int i = 0; i < 4; i++)
                ra[i] = ((const float4*)(c0s + (4 * rp + i) * 260))[j4];
            #pragma unroll
            for (int j = 0; j < 4; j++)
                rb[j] = ((const float4*)(c0s + (4 * cg + j) * 260))[j4];
            #pragma unroll
            for (int i = 0; i < 4; i++)
                #pragma unroll
                for (int j = 0; j < 4; j++)
                    acc[i][j] += ra[i].x * rb[j].x + ra[i].y * rb[j].y
                               + ra[i].z * rb[j].z + ra[i].w * rb[j].w;
        }
    }

    #pragma unroll
    for (int i = 0; i < 4; i++)
        #pragma unroll
        for (int j = 0; j < 4; j++) {
            float v = acc[i][j];
            v += __shfl_xor_sync(0xffffffffu, v, 1);
            v += __shfl_xor_sync(0xffffffffu, v, 2);
            v += __shfl_xor_sync(0xffffffffu, v, 4);
            v += __shfl_xor_sync(0xffffffffu, v, 8);
            acc[i][j] = v;
        }
    if (p == 0) {
        float* dst = g_gpart + (chunk * BATCH + b) * 256;
        #pragma unroll
        for (int i = 0; i < 4; i++)
            #pragma unroll
            for (int j = 0; j < 4; j++)
                dst[(4 * rp + i) * 16 + 4 * cg + j] = acc[i][j];
    }
}

// ---------------------------------------------------------------------------
// Kernel 2: sum partials, softmax + fold into W_eff
// ---------------------------------------------------------------------------
__global__ __launch_bounds__(256) void fold_kernel(
    const float* __restrict__ beta_cam,
    const float* __restrict__ wc2, const float* __restrict__ g2,
    const float* __restrict__ v2)
{
    __shared__ float gsm[256];
    __shared__ float asmem[256];
    const int b = blockIdx.x;
    const int t = threadIdx.x;

    float s = 0.f;
    #pragma unroll
    for (int ch = 0; ch < NCHUNK; ch++)
        s += g_gpart[(ch * BATCH + b) * 256 + t];
    gsm[t] = s;
    __syncthreads();

    if (t < 16) {
        float rmin = 1e30f;
        #pragma unroll
        for (int d = 0; d < 16; d++) rmin = fminf(rmin, gsm[t * 16 + d]);
        float e[16];
        float ssum = 0.f;
        #pragma unroll
        for (int d = 0; d < 16; d++) { e[d] = expf(rmin - gsm[t * 16 + d]); ssum += e[d]; }
        float invs = 1.f / ssum;
        #pragma unroll
        for (int d = 0; d < 16; d++) asmem[t * 16 + d] = e[d] * invs;
    }
    __syncthreads();

    const int cg = t >> 4;
    const int dg = t & 15;
    float inv2c = g2[cg] * rsqrtf(v2[cg] + EPSB);
    float beta = beta_cam[0];
    float acc = 0.f;
    #pragma unroll
    for (int e = 0; e < 16; e++) acc += wc2[cg * 16 + e] * asmem[e * 16 + dg];
    g_Weff[b * 256 + t] = inv2c * (beta * acc + wc2[cg * 16 + dg]);
}

// ---------------------------------------------------------------------------
// Kernel 3: fused ConvFusion + attention epilogue. (R1 main, measured 340us)
// Grid (L/TL, B), 256 threads. Per block: 512 output positions, all 16 ch.
// ---------------------------------------------------------------------------
__global__ __launch_bounds__(256) void main_kernel(
    const float* __restrict__ x,
    const float* __restrict__ w00, const float* __restrict__ b00,
    const float* __restrict__ w01, const float* __restrict__ b01,
    const float* __restrict__ w02, const float* __restrict__ b02,
    const float* __restrict__ wc1, const float* __restrict__ g1,
    const float* __restrict__ bt1, const float* __restrict__ m1,
    const float* __restrict__ v1,
    const float* __restrict__ g2, const float* __restrict__ bt2,
    const float* __restrict__ m2, const float* __restrict__ v2,
    float* __restrict__ out)
{
    __shared__ float xs[4 * 580];      // x[l0-32 .. l0+TL+33], zero padded
    __shared__ float f0s[8 * 544];     // fea0 for j in [l0-14, l0+TL+16]
    __shared__ float w00s[1024];       // [d][i][k]
    __shared__ float w01t[1024];       // [d][k][c]
    __shared__ float w02t[1024];       // [d][k][c]
    __shared__ float u1s[64];          // [c][i] (inv1 folded)
    __shared__ float sh1s[16];
    __shared__ float sh2s[16];
    __shared__ float weffs[256];
    __shared__ float b00s[8], b01s[8], b02s[8];

    const int t = threadIdx.x;
    const int l0 = blockIdx.x * TL;
    const int b = blockIdx.y;

    // ---- phase A: weights into SMEM ----
    for (int i = t; i < 1024; i += 256) w00s[i] = w00[i];
    for (int i = t; i < 1024; i += 256) {
        int d = i >> 7, k = (i >> 3) & 15, c = i & 7;
        w01t[i] = w01[(c * 8 + d) * 16 + k];
        w02t[i] = w02[(c * 8 + d) * 16 + k];
    }
    if (t < 64) {
        int c = t >> 2;
        float inv1 = g1[c] * rsqrtf(v1[c] + EPSB);
        u1s[t] = inv1 * wc1[t];
    }
    if (t < 16) {
        float inv1 = g1[t] * rsqrtf(v1[t] + EPSB);
        sh1s[t] = bt1[t] - m1[t] * inv1;
        float inv2 = g2[t] * rsqrtf(v2[t] + EPSB);
        sh2s[t] = bt2[t] - m2[t] * inv2;
    }
    weffs[t] = g_Weff[b * 256 + t];
    if (t < 8) { b00s[t] = b00[t]; b01s[t] = b01[t]; b02s[t] = b02[t]; }

    // ---- phase B: x tile (with halo, zero padded) ----
    for (int idx = t; idx < 4 * 580; idx += 256) {
        int i = idx / 580, o = idx - i * 580;
        int g = l0 - 32 + o;
        xs[idx] = (g >= 0 && g < LLEN) ? x[(b * 4 + i) * LLEN + g] : 0.f;
    }
    __syncthreads();

    // ---- phase C: fea0 into SMEM. warp w owns channel d=w; lane owns 17 pos ----
    {
        const int d = t >> 5;
        const int lane = t & 31;
        const int jj0 = lane * 17;
        float acc[17];
        #pragma unroll
        for (int p = 0; p < 17; p++) acc[p] = 0.f;
        for (int i = 0; i < 4; i++) {
            float xw[48];
            const float* xrow = xs + i * 580 + jj0 + 2;
            #pragma unroll
            for (int m = 0; m < 48; m++) xw[m] = xrow[m];
            const float* wrow = w00s + (d * 4 + i) * 32;
            #pragma unroll
            for (int k = 0; k < 32; k++) {
                float wv = wrow[k];
                #pragma unroll
                for (int p = 0; p < 17; p++) acc[p] += wv * xw[p + k];
            }
        }
        float bv = b00s[d];
        #pragma unroll
        for (int p = 0; p < 17; p++) {
            int jj = jj0 + p;
            int j = l0 - 14 + jj;
            f0s[d * 544 + jj] = (j >= 0 && j <= LLEN) ? (acc[p] + bv) : 0.f;
        }
    }
    __syncthreads();

    // ---- phase D: fea1/fea2 + c0 + folded attention epilogue ----
    {
        float accA[2][8], accB[2][8];
        #pragma unroll
        for (int c = 0; c < 8; c++) {
            accA[0][c] = b01s[c]; accA[1][c] = b01s[c];
            accB[0][c] = b02s[c]; accB[1][c] = b02s[c];
        }
        const int base2 = 2 * t;

        for (int d = 0; d < 8; d++) {
            float win[32];
            const float2* fr = (const float2*)(f0s + d * 544 + base2);
            #pragma unroll
            for (int j2 = 0; j2 < 16; j2++) {
                float2 v = fr[j2];
                win[2 * j2] = v.x; win[2 * j2 + 1] = v.y;
            }
            const float* w1r = w01t + d * 128;
            const float* w2r = w02t + d * 128;
            #pragma unroll
            for (int k = 0; k < 16; k++) {
                float4 a0 = *(const float4*)(w1r + k * 8);
                float4 a1 = *(const float4*)(w1r + k * 8 + 4);
                float4 e0 = *(const float4*)(w2r + k * 8);
                float4 e1 = *(const float4*)(w2r + k * 8 + 4);
                float wA[8] = {a0.x, a0.y, a0.z, a0.w, a1.x, a1.y, a1.z, a1.w};
                float wB[8] = {e0.x, e0.y, e0.z, e0.w, e1.x, e1.y, e1.z, e1.w};
                float fA0 = win[7 + k], fA1 = win[8 + k];
                float fB0 = win[2 * k], fB1 = win[2 * k + 1];
                #pragma unroll
                for (int c = 0; c < 8; c++) {
                    accA[0][c] += wA[c] * fA0;
                    accA[1][c] += wA[c] * fA1;
                    accB[0][c] += wB[c] * fB0;
                    accB[1][c] += wB[c] * fB1;
                }
            }
        }

        // c0 for both positions
        float c0v[2][16];
        #pragma unroll
        for (int p = 0; p < 2; p++) {
            int o = 32 + base2 + p;
            float x0 = xs[0 * 580 + o], x1 = xs[1 * 580 + o];
            float x2 = xs[2 * 580 + o], x3 = xs[3 * 580 + o];
            #pragma unroll
            for (int c = 0; c < 16; c++) {
                float4 u = *(const float4*)(u1s + c * 4);
                float v = sh1s[c] + u.x * x0 + u.y * x1 + u.z * x2 + u.w * x3;
                c0v[p][c] = fmaxf(v, 0.f);
            }
        }

        const int l = l0 + base2;
        #pragma unroll
        for (int c = 0; c < 16; c++) {
            float s0 = sh2s[c], s1 = sh2s[c];
            #pragma unroll
            for (int dq = 0; dq < 16; dq += 4) {
                float4 wv = *(const float4*)(weffs + c * 16 + dq);
                s0 += wv.x * c0v[0][dq] + wv.y * c0v[0][dq + 1]
                    + wv.z * c0v[0][dq + 2] + wv.w * c0v[0][dq + 3];
                s1 += wv.x * c0v[1][dq] + wv.y * c0v[1][dq + 1]
                    + wv.z * c0v[1][dq + 2] + wv.w * c0v[1][dq + 3];
            }
            float f0v, f1v;
            if (c < 8) {
                f0v = accA[0][c]; f1v = accA[1][c];
            } else {
                f0v = accB[0][c - 8]; f1v = accB[1][c - 8];
                if (l == 0 || l >= LLEN - 2) f0v = 0.f;
                if (l + 1 >= LLEN - 2) f1v = 0.f;
            }
            float2 ov;
            ov.x = f0v + fmaxf(s0, 0.f);
            ov.y = f1v + fmaxf(s1, 0.f);
            *(float2*)(out + (b * 16 + c) * LLEN + l) = ov;
        }
    }
}

// ---------------------------------------------------------------------------
extern "C" void kernel_launch(void* const* d_in, const int* in_sizes, int n_in,
                              void* d_out, int out_size)
{
    const float* x        = (const float*)d_in[0];
    const float* w00      = (const float*)d_in[1];
    const float* b00      = (const float*)d_in[2];
    const float* w01      = (const float*)d_in[3];
    const float* b01      = (const float*)d_in[4];
    const float* w02      = (const float*)d_in[5];
    const float* b02      = (const float*)d_in[6];
    const float* wc1      = (const float*)d_in[7];
    const float* g1       = (const float*)d_in[8];
    const float* bt1      = (const float*)d_in[9];
    const float* m1       = (const float*)d_in[10];
    const float* v1       = (const float*)d_in[11];
    const float* beta_cam = (const float*)d_in[12];
    const float* wc2      = (const float*)d_in[13];
    const float* g2       = (const float*)d_in[14];
    const float* bt2      = (const float*)d_in[15];
    const float* m2       = (const float*)d_in[16];
    const float* v2       = (const float*)d_in[17];
    float* out = (float*)d_out;

    dim3 ggrid(NCHUNK, BATCH);
    gram_kernel<<<ggrid, 256>>>(x, wc1, g1, bt1, m1, v1);
    fold_kernel<<<BATCH, 256>>>(beta_cam, wc2, g2, v2);
    dim3 grid(LLEN / TL, BATCH);
    main_kernel<<<grid, 256>>>(x, w00, b00, w01, b01, w02, b02,
                               wc1, g1, bt1, m1, v1, g2, bt2, m2, v2, out);
}

// round 10
// speedup vs baseline: 2.2395x; 1.0318x over previous
#include <cuda_runtime.h>
#include <math.h>

#define LLEN 8192
#define BATCH 256
#define TL 512
#define EPSB 1e-5f
#define NCHUNK 8

typedef unsigned long long u64;

// ---------------- f32x2 helpers ----------------
__device__ __forceinline__ u64 f2(u64 a, u64 b, u64 c) {
    u64 d;
    asm("fma.rn.f32x2 %0, %1, %2, %3;" : "=l"(d) : "l"(a), "l"(b), "l"(c));
    return d;
}
__device__ __forceinline__ u64 pk(float lo, float hi) {
    u64 d;
    asm("mov.b64 %0, {%1, %2};" : "=l"(d) : "f"(lo), "f"(hi));
    return d;
}
__device__ __forceinline__ float lo2(u64 v) {
    float f;
    asm("{.reg .f32 h;\n\tmov.b64 {%0, h}, %1;}" : "=f"(f) : "l"(v));
    return f;
}
__device__ __forceinline__ float hi2(u64 v) {
    float f;
    asm("{.reg .f32 l;\n\tmov.b64 {l, %0}, %1;}" : "=f"(f) : "l"(v));
    return f;
}

// ---------------- device scratch ----------------
__device__ float g_gpart[NCHUNK * BATCH * 256];
__device__ float g_Weff[BATCH * 256];

// ---------------------------------------------------------------------------
// Kernel 1: partial gram of c0, 4x4 register tiling. (measured 67us — frozen)
// ---------------------------------------------------------------------------
__global__ __launch_bounds__(256) void gram_kernel(
    const float* __restrict__ x,
    const float* __restrict__ wc1, const float* __restrict__ g1,
    const float* __restrict__ bt1, const float* __restrict__ m1,
    const float* __restrict__ v1)
{
    __shared__ float c0s[16 * 260];
    __shared__ float u1s[64];
    __shared__ float sh1s[16];

    const int b = blockIdx.y;
    const int chunk = blockIdx.x;
    const int t = threadIdx.x;
    const int rp = t >> 6;
    const int cg = (t >> 4) & 3;
    const int p  = t & 15;

    if (t < 16) {
        float inv1 = g1[t] * rsqrtf(v1[t] + EPSB);
        sh1s[t] = bt1[t] - m1[t] * inv1;
        #pragma unroll
        for (int i = 0; i < 4; i++) u1s[t * 4 + i] = inv1 * wc1[t * 4 + i];
    }
    __syncthreads();

    const volatile float* uv = u1s;
    const volatile float* sv = sh1s;

    float acc[4][4];
    #pragma unroll
    for (int i = 0; i < 4; i++)
        #pragma unroll
        for (int j = 0; j < 4; j++) acc[i][j] = 0.f;

    for (int ch = 0; ch < 4; ch++) {
        int pos = (chunk * 4 + ch) * 256 + t;
        float xv0 = x[(b * 4 + 0) * LLEN + pos];
        float xv1 = x[(b * 4 + 1) * LLEN + pos];
        float xv2 = x[(b * 4 + 2) * LLEN + pos];
        float xv3 = x[(b * 4 + 3) * LLEN + pos];
        __syncthreads();
        #pragma unroll
        for (int c = 0; c < 16; c++) {
            float v = sv[c] + uv[c * 4 + 0] * xv0 + uv[c * 4 + 1] * xv1
                            + uv[c * 4 + 2] * xv2 + uv[c * 4 + 3] * xv3;
            c0s[c * 260 + t] = fmaxf(v, 0.f);
        }
        __syncthreads();
        #pragma unroll
        for (int m = 0; m < 4; m++) {
            int j4 = p + 16 * m;
            float4 ra[4], rb[4];
            #pragma unroll
            for (int i = 0; i < 4; i++)
                ra[i] = ((const float4*)(c0s + (4 * rp + i) * 260))[j4];
            #pragma unroll
            for (int j = 0; j < 4; j++)
                rb[j] = ((const float4*)(c0s + (4 * cg + j) * 260))[j4];
            #pragma unroll
            for (int i = 0; i < 4; i++)
                #pragma unroll
                for (int j = 0; j < 4; j++)
                    acc[i][j] += ra[i].x * rb[j].x + ra[i].y * rb[j].y
                               + ra[i].z * rb[j].z + ra[i].w * rb[j].w;
        }
    }

    #pragma unroll
    for (int i = 0; i < 4; i++)
        #pragma unroll
        for (int j = 0; j < 4; j++) {
            float v = acc[i][j];
            v += __shfl_xor_sync(0xffffffffu, v, 1);
            v += __shfl_xor_sync(0xffffffffu, v, 2);
            v += __shfl_xor_sync(0xffffffffu, v, 4);
            v += __shfl_xor_sync(0xffffffffu, v, 8);
            acc[i][j] = v;
        }
    if (p == 0) {
        float* dst = g_gpart + (chunk * BATCH + b) * 256;
        #pragma unroll
        for (int i = 0; i < 4; i++)
            #pragma unroll
            for (int j = 0; j < 4; j++)
                dst[(4 * rp + i) * 16 + 4 * cg + j] = acc[i][j];
    }
}

// ---------------------------------------------------------------------------
// Kernel 2: sum partials, softmax + fold into W_eff
// ---------------------------------------------------------------------------
__global__ __launch_bounds__(256) void fold_kernel(
    const float* __restrict__ beta_cam,
    const float* __restrict__ wc2, const float* __restrict__ g2,
    const float* __restrict__ v2)
{
    __shared__ float gsm[256];
    __shared__ float asmem[256];
    const int b = blockIdx.x;
    const int t = threadIdx.x;

    float s = 0.f;
    #pragma unroll
    for (int ch = 0; ch < NCHUNK; ch++)
        s += g_gpart[(ch * BATCH + b) * 256 + t];
    gsm[t] = s;
    __syncthreads();

    if (t < 16) {
        float rmin = 1e30f;
        #pragma unroll
        for (int d = 0; d < 16; d++) rmin = fminf(rmin, gsm[t * 16 + d]);
        float e[16];
        float ssum = 0.f;
        #pragma unroll
        for (int d = 0; d < 16; d++) { e[d] = expf(rmin - gsm[t * 16 + d]); ssum += e[d]; }
        float invs = 1.f / ssum;
        #pragma unroll
        for (int d = 0; d < 16; d++) asmem[t * 16 + d] = e[d] * invs;
    }
    __syncthreads();

    const int cg = t >> 4;
    const int dg = t & 15;
    float inv2c = g2[cg] * rsqrtf(v2[cg] + EPSB);
    float beta = beta_cam[0];
    float acc = 0.f;
    #pragma unroll
    for (int e = 0; e < 16; e++) acc += wc2[cg * 16 + e] * asmem[e * 16 + dg];
    g_Weff[b * 256 + t] = inv2c * (beta * acc + wc2[cg * 16 + dg]);
}

// ---------------------------------------------------------------------------
// Kernel 3: fused ConvFusion + attention epilogue.
// R9 main with phase D packed over channel pairs (fma.rn.f32x2) and the
// weff epilogue packed over dq pairs. Zero extra SMEM traffic vs R9.
// ---------------------------------------------------------------------------
__global__ __launch_bounds__(256) void main_kernel(
    const float* __restrict__ x,
    const float* __restrict__ w00, const float* __restrict__ b00,
    const float* __restrict__ w01, const float* __restrict__ b01,
    const float* __restrict__ w02, const float* __restrict__ b02,
    const float* __restrict__ wc1, const float* __restrict__ g1,
    const float* __restrict__ bt1, const float* __restrict__ m1,
    const float* __restrict__ v1,
    const float* __restrict__ g2, const float* __restrict__ bt2,
    const float* __restrict__ m2, const float* __restrict__ v2,
    float* __restrict__ out)
{
    __shared__ float xs[4 * 580];
    __shared__ float f0s[8 * 544];
    __shared__ float w00s[1024];
    __shared__ float w01t[1024];       // [d][k][c]
    __shared__ float w02t[1024];       // [d][k][c]
    __shared__ float u1s[64];
    __shared__ float sh1s[16];
    __shared__ float sh2s[16];
    __shared__ float weffs[256];
    __shared__ float b00s[8], b01s[8], b02s[8];

    const int t = threadIdx.x;
    const int l0 = blockIdx.x * TL;
    const int b = blockIdx.y;

    // ---- phase A: weights into SMEM ----
    for (int i = t; i < 1024; i += 256) w00s[i] = w00[i];
    for (int i = t; i < 1024; i += 256) {
        int d = i >> 7, k = (i >> 3) & 15, c = i & 7;
        w01t[i] = w01[(c * 8 + d) * 16 + k];
        w02t[i] = w02[(c * 8 + d) * 16 + k];
    }
    if (t < 64) {
        int c = t >> 2;
        float inv1 = g1[c] * rsqrtf(v1[c] + EPSB);
        u1s[t] = inv1 * wc1[t];
    }
    if (t < 16) {
        float inv1 = g1[t] * rsqrtf(v1[t] + EPSB);
        sh1s[t] = bt1[t] - m1[t] * inv1;
        float inv2 = g2[t] * rsqrtf(v2[t] + EPSB);
        sh2s[t] = bt2[t] - m2[t] * inv2;
    }
    weffs[t] = g_Weff[b * 256 + t];
    if (t < 8) { b00s[t] = b00[t]; b01s[t] = b01[t]; b02s[t] = b02[t]; }

    // ---- phase B: x tile (with halo, zero padded) ----
    for (int idx = t; idx < 4 * 580; idx += 256) {
        int i = idx / 580, o = idx - i * 580;
        int g = l0 - 32 + o;
        xs[idx] = (g >= 0 && g < LLEN) ? x[(b * 4 + i) * LLEN + g] : 0.f;
    }
    __syncthreads();

    // ---- phase C: fea0 into SMEM. warp w owns channel d=w; lane owns 17 pos ----
    {
        const int d = t >> 5;
        const int lane = t & 31;
        const int jj0 = lane * 17;
        float acc[17];
        #pragma unroll
        for (int p = 0; p < 17; p++) acc[p] = 0.f;
        for (int i = 0; i < 4; i++) {
            float xw[48];
            const float* xrow = xs + i * 580 + jj0 + 2;
            #pragma unroll
            for (int m = 0; m < 48; m++) xw[m] = xrow[m];
            const float* wrow = w00s + (d * 4 + i) * 32;
            #pragma unroll
            for (int k = 0; k < 32; k++) {
                float wv = wrow[k];
                #pragma unroll
                for (int p = 0; p < 17; p++) acc[p] += wv * xw[p + k];
            }
        }
        float bv = b00s[d];
        #pragma unroll
        for (int p = 0; p < 17; p++) {
            int jj = jj0 + p;
            int j = l0 - 14 + jj;
            f0s[d * 544 + jj] = (j >= 0 && j <= LLEN) ? (acc[p] + bv) : 0.f;
        }
    }
    __syncthreads();

    // ---- phase D: fea1/fea2 packed over channel pairs ----
    {
        const int base2 = 2 * t;
        // accumulator pairs: aA[p][c2] holds channels (2c2, 2c2+1)
        u64 aA[2][4], aB[2][4];
        #pragma unroll
        for (int c2 = 0; c2 < 4; c2++) {
            u64 bA = pk(b01s[2 * c2], b01s[2 * c2 + 1]);
            u64 bB = pk(b02s[2 * c2], b02s[2 * c2 + 1]);
            aA[0][c2] = bA; aA[1][c2] = bA;
            aB[0][c2] = bB; aB[1][c2] = bB;
        }

        for (int d = 0; d < 8; d++) {
            float win[32];
            const float2* fr = (const float2*)(f0s + d * 544 + base2);
            #pragma unroll
            for (int j2 = 0; j2 < 16; j2++) {
                float2 v = fr[j2];
                win[2 * j2] = v.x; win[2 * j2 + 1] = v.y;
            }
            const longlong2* w1r2 = (const longlong2*)(w01t + d * 128);
            const longlong2* w2r2 = (const longlong2*)(w02t + d * 128);
            #pragma unroll
            for (int k = 0; k < 16; k++) {
                longlong2 wa0 = w1r2[2 * k];       // ch pairs (0,1),(2,3)
                longlong2 wa1 = w1r2[2 * k + 1];   // ch pairs (4,5),(6,7)
                longlong2 wb0 = w2r2[2 * k];
                longlong2 wb1 = w2r2[2 * k + 1];
                u64 fA0 = pk(win[7 + k], win[7 + k]);
                u64 fA1 = pk(win[8 + k], win[8 + k]);
                u64 fB0 = pk(win[2 * k], win[2 * k]);
                u64 fB1 = pk(win[2 * k + 1], win[2 * k + 1]);
                aA[0][0] = f2((u64)wa0.x, fA0, aA[0][0]);
                aA[0][1] = f2((u64)wa0.y, fA0, aA[0][1]);
                aA[0][2] = f2((u64)wa1.x, fA0, aA[0][2]);
                aA[0][3] = f2((u64)wa1.y, fA0, aA[0][3]);
                aA[1][0] = f2((u64)wa0.x, fA1, aA[1][0]);
                aA[1][1] = f2((u64)wa0.y, fA1, aA[1][1]);
                aA[1][2] = f2((u64)wa1.x, fA1, aA[1][2]);
                aA[1][3] = f2((u64)wa1.y, fA1, aA[1][3]);
                aB[0][0] = f2((u64)wb0.x, fB0, aB[0][0]);
                aB[0][1] = f2((u64)wb0.y, fB0, aB[0][1]);
                aB[0][2] = f2((u64)wb1.x, fB0, aB[0][2]);
                aB[0][3] = f2((u64)wb1.y, fB0, aB[0][3]);
                aB[1][0] = f2((u64)wb0.x, fB1, aB[1][0]);
                aB[1][1] = f2((u64)wb0.y, fB1, aB[1][1]);
                aB[1][2] = f2((u64)wb1.x, fB1, aB[1][2]);
                aB[1][3] = f2((u64)wb1.y, fB1, aB[1][3]);
            }
        }

        // ---- c0 for both positions (scalar), then pack over dq pairs ----
        float c0v[2][16];
        #pragma unroll
        for (int p = 0; p < 2; p++) {
            int o = 32 + base2 + p;
            float x0 = xs[0 * 580 + o], x1 = xs[1 * 580 + o];
            float x2 = xs[2 * 580 + o], x3 = xs[3 * 580 + o];
            #pragma unroll
            for (int c = 0; c < 16; c++) {
                float4 u = *(const float4*)(u1s + c * 4);
                float v = sh1s[c] + u.x * x0 + u.y * x1 + u.z * x2 + u.w * x3;
                c0v[p][c] = fmaxf(v, 0.f);
            }
        }
        u64 c0p[2][8];
        #pragma unroll
        for (int p = 0; p < 2; p++)
            #pragma unroll
            for (int q = 0; q < 8; q++)
                c0p[p][q] = pk(c0v[p][2 * q], c0v[p][2 * q + 1]);

        const int l = l0 + base2;
        #pragma unroll
        for (int c = 0; c < 16; c++) {
            const longlong2* wr = (const longlong2*)(weffs + c * 16);
            u64 s0p = pk(sh2s[c], 0.f);
            u64 s1p = pk(sh2s[c], 0.f);
            #pragma unroll
            for (int q2 = 0; q2 < 4; q2++) {
                longlong2 wv = wr[q2];
                s0p = f2((u64)wv.x, c0p[0][2 * q2], s0p);
                s0p = f2((u64)wv.y, c0p[0][2 * q2 + 1], s0p);
                s1p = f2((u64)wv.x, c0p[1][2 * q2], s1p);
                s1p = f2((u64)wv.y, c0p[1][2 * q2 + 1], s1p);
            }
            float s0 = lo2(s0p) + hi2(s0p);
            float s1 = lo2(s1p) + hi2(s1p);
            float f0v, f1v;
            if (c < 8) {
                int c2 = c >> 1;
                f0v = (c & 1) ? hi2(aA[0][c2]) : lo2(aA[0][c2]);
                f1v = (c & 1) ? hi2(aA[1][c2]) : lo2(aA[1][c2]);
            } else {
                int c2 = (c - 8) >> 1;
                f0v = (c & 1) ? hi2(aB[0][c2]) : lo2(aB[0][c2]);
                f1v = (c & 1) ? hi2(aB[1][c2]) : lo2(aB[1][c2]);
                if (l == 0 || l >= LLEN - 2) f0v = 0.f;
                if (l + 1 >= LLEN - 2) f1v = 0.f;
            }
            float2 ov;
            ov.x = f0v + fmaxf(s0, 0.f);
            ov.y = f1v + fmaxf(s1, 0.f);
            *(float2*)(out + (b * 16 + c) * LLEN + l) = ov;
        }
    }
}

// ---------------------------------------------------------------------------
extern "C" void kernel_launch(void* const* d_in, const int* in_sizes, int n_in,
                              void* d_out, int out_size)
{
    const float* x        = (const float*)d_in[0];
    const float* w00      = (const float*)d_in[1];
    const float* b00      = (const float*)d_in[2];
    const float* w01      = (const float*)d_in[3];
    const float* b01      = (const float*)d_in[4];
    const float* w02      = (const float*)d_in[5];
    const float* b02      = (const float*)d_in[6];
    const float* wc1      = (const float*)d_in[7];
    const float* g1       = (const float*)d_in[8];
    const float* bt1      = (const float*)d_in[9];
    const float* m1       = (const float*)d_in[10];
    const float* v1       = (const float*)d_in[11];
    const float* beta_cam = (const float*)d_in[12];
    const float* wc2      = (const float*)d_in[13];
    const float* g2       = (const float*)d_in[14];
    const float* bt2      = (const float*)d_in[15];
    const float* m2       = (const float*)d_in[16];
    const float* v2       = (const float*)d_in[17];
    float* out = (float*)d_out;

    dim3 ggrid(NCHUNK, BATCH);
    gram_kernel<<<ggrid, 256>>>(x, wc1, g1, bt1, m1, v1);
    fold_kernel<<<BATCH, 256>>>(beta_cam, wc2, g2, v2);
    dim3 grid(LLEN / TL, BATCH);
    main_kernel<<<grid, 256>>>(x, w00, b00, w01, b01, w02, b02,
                               wc1, g1, bt1, m1, v1, g2, bt2, m2, v2, out);
}